// round 2
// baseline (speedup 1.0000x reference)
#include <cuda_runtime.h>
#include <cstdint>
#include <cmath>

#define GH 512
#define GK 50
#define GT 1024
#define GB 128
#define GM (GB * GT)
#define BPP 52

// Scratch for projected features [B*T, K]
__device__ float g_feats[(size_t)GM * GK];

// Packed fp32x2 FMA (sm_103a): acc = x * w + acc
#define FFMA2(acc, x, w) \
    asm("fma.rn.f32x2 %0, %1, %2, %0;" : "+l"(acc) : "l"(x), "l"(w))

// ---------------------------------------------------------------------------
// Kernel 1: feats[m][k] = sum_h hidden[m][h] * W[k][h] + b[k]
// 256 CTAs x 256 threads, 2 rows/thread, 512 rows/CTA.
// hidden staged through smem (coalesced LDG: 4 lanes share 64B of one row ->
// 8 L1 wavefronts per LDG.128 instead of 32), double-buffered 16-h chunks.
// W transposed in smem [h][52]; broadcast LDS.128 (conflict-free).
// ---------------------------------------------------------------------------
#define RPC 512           // rows per CTA
#define CH 16             // h per chunk
#define NCH (GH / CH)     // 32 chunks
#define SROW 20           // stage row pad (floats): 80B, 16B-aligned, LDS.128 conflict-free
#define WT_FLOATS (GH * 52)          // 26624
#define STG_FLOATS (RPC * SROW)      // 10240 per buffer

__global__ __launch_bounds__(256, 1) void gemm_kernel(
    const float* __restrict__ hidden, const float* __restrict__ W,
    const float* __restrict__ bias) {
    extern __shared__ float sm[];
    float* Wt  = sm;                  // [512][52]
    float* stg = sm + WT_FLOATS;      // [2][512][20]
    const int tid = threadIdx.x;

    // Transpose W: W[k*512+h] -> Wt[h*52+k]  (coalesced gmem reads)
    for (int idx = tid; idx < GK * GH; idx += 256) {
        int k = idx >> 9;
        int h = idx & 511;
        Wt[h * 52 + k] = W[idx];
    }

    const size_t base = (size_t)blockIdx.x * RPC;

    unsigned long long acc0[25], acc1[25];
#pragma unroll
    for (int q = 0; q < 25; q++) { acc0[q] = 0ull; acc1[q] = 0ull; }

    // Preload chunk 0 into stage buffer 0
    {
        float4 pf[8];
#pragma unroll
        for (int p = 0; p < 8; p++) {
            int f = tid + 256 * p;
            int row = f >> 2, q = f & 3;
            pf[p] = *reinterpret_cast<const float4*>(hidden + (base + row) * GH + q * 4);
        }
#pragma unroll
        for (int p = 0; p < 8; p++) {
            int f = tid + 256 * p;
            int row = f >> 2, q = f & 3;
            *reinterpret_cast<float4*>(stg + row * SROW + q * 4) = pf[p];
        }
    }
    __syncthreads();

    for (int hc = 0; hc < NCH; hc++) {
        const int cb = hc & 1;
        float4 pf[8];
        if (hc + 1 < NCH) {
#pragma unroll
            for (int p = 0; p < 8; p++) {
                int f = tid + 256 * p;
                int row = f >> 2, q = f & 3;
                pf[p] = *reinterpret_cast<const float4*>(
                    hidden + (base + row) * GH + (hc + 1) * CH + q * 4);
            }
        }

        // Read this thread's 2 rows x 16 h from stage into registers
        const float* cbp = stg + cb * STG_FLOATS;
        float4 xa[4], xb[4];
#pragma unroll
        for (int q = 0; q < 4; q++) {
            xa[q] = *reinterpret_cast<const float4*>(cbp + tid * SROW + q * 4);
            xb[q] = *reinterpret_cast<const float4*>(cbp + (tid + 256) * SROW + q * 4);
        }

#pragma unroll
        for (int u = 0; u < CH; u++) {
            const float fx0 = reinterpret_cast<const float*>(xa)[u];
            const float fx1 = reinterpret_cast<const float*>(xb)[u];
            unsigned long long X0, X1;
            asm("mov.b64 %0, {%1, %1};" : "=l"(X0) : "r"(__float_as_uint(fx0)));
            asm("mov.b64 %0, {%1, %1};" : "=l"(X1) : "r"(__float_as_uint(fx1)));
            const float* wr = Wt + (hc * CH + u) * 52;
#pragma unroll
            for (int q = 0; q < 12; q++) {
                ulonglong2 w = *reinterpret_cast<const ulonglong2*>(wr + q * 4);
                FFMA2(acc0[2 * q],     X0, w.x);
                FFMA2(acc0[2 * q + 1], X0, w.y);
                FFMA2(acc1[2 * q],     X1, w.x);
                FFMA2(acc1[2 * q + 1], X1, w.y);
            }
            unsigned long long wl = *reinterpret_cast<const unsigned long long*>(wr + 48);
            FFMA2(acc0[24], X0, wl);
            FFMA2(acc1[24], X1, wl);
        }

        if (hc + 1 < NCH) {
            float* nbp = stg + ((hc + 1) & 1) * STG_FLOATS;
#pragma unroll
            for (int p = 0; p < 8; p++) {
                int f = tid + 256 * p;
                int row = f >> 2, q = f & 3;
                *reinterpret_cast<float4*>(nbp + row * SROW + q * 4) = pf[p];
            }
            __syncthreads();
        }
    }

    // Epilogue: bias + store feats rows (float2, 8B aligned since 50 even)
    float2* o0 = reinterpret_cast<float2*>(g_feats + (base + tid) * GK);
    float2* o1 = reinterpret_cast<float2*>(g_feats + (base + tid + 256) * GK);
    const float2* bb = reinterpret_cast<const float2*>(bias);
#pragma unroll
    for (int q = 0; q < 25; q++) {
        float2 bv = bb[q];
        float2 v0 = *reinterpret_cast<float2*>(&acc0[q]);
        float2 v1 = *reinterpret_cast<float2*>(&acc1[q]);
        v0.x += bv.x; v0.y += bv.y;
        v1.x += bv.x; v1.y += bv.y;
        o0[q] = v0;
        o1[q] = v1;
    }
}

// ---------------------------------------------------------------------------
// Pairwise argmax tree: adjacent pairs keep index-ordered subranges, so a
// strict '>' (take right only if strictly greater) implements jnp.argmax
// first-max tie-breaking exactly. Fully unrolled via template recursion.
// ---------------------------------------------------------------------------
template <int W>
__device__ __forceinline__ void argmax_tree(float* val, int* id) {
    if constexpr (W > 1) {
        constexpr int P = W >> 1;
#pragma unroll
        for (int m = 0; m < P; m++) {
            bool g = val[2 * m + 1] > val[2 * m];
            val[m] = g ? val[2 * m + 1] : val[2 * m];
            id[m]  = g ? id[2 * m + 1]  : id[2 * m];
        }
        if constexpr (W & 1) { val[P] = val[W - 1]; id[P] = id[W - 1]; }
        argmax_tree<((W + 1) >> 1)>(val, id);
    }
}

// ---------------------------------------------------------------------------
// Kernel 2: fused Viterbi forward + backtrace. One CTA (128 thr, 4 warps)
// per batch. Thread (j, r): j = tid>>1, r = tid&1; r=0 covers i in [0,28),
// r=1 covers i in [24,52) (overlap + -inf pad is fine: lexicographic
// (val, -idx) max is associative). Tree argmax depth 5 + ONE shfl merge.
// Backpointers in smem -> backtrace is an LDS pointer chase.
// ---------------------------------------------------------------------------
__global__ __launch_bounds__(128, 1) void viterbi_kernel(
    const float* __restrict__ trans, const float* __restrict__ startt,
    const float* __restrict__ stopt, float* __restrict__ out) {
    extern __shared__ char smv[];
    unsigned char* bp = reinterpret_cast<unsigned char*>(smv);       // 1023*52 = 53196
    float* vbuf = reinterpret_cast<float*>(smv + 53200);             // [2][64]
    float* red  = vbuf + 128;                                        // [64]
    unsigned char* tags = reinterpret_cast<unsigned char*>(red + 64); // [1024]

    const int b = blockIdx.x;
    const int tid = threadIdx.x;
    const int j = tid >> 1;
    const int r = tid & 1;
    const float* F = g_feats + (size_t)b * GT * GK;
    const int i0 = r ? 24 : 0;

    // Per-thread transition slice trans[i][j], i in [i0, i0+28), pad -inf
    float tr[28];
#pragma unroll
    for (int ii = 0; ii < 28; ii++) {
        int i = i0 + ii;
        tr[ii] = (j < GK && i < GK) ? trans[i * GK + j] : -INFINITY;
    }

    // Pad unused state slots with -inf in both v buffers (slots 50..63)
    if ((tid & 63) >= GK) { vbuf[tid] = -INFINITY; }
    if (r == 0 && j < GK) vbuf[j] = F[j] + startt[j];

    // Feats prefetch ring, depth 4
    float fr[4];
    if (r == 0 && j < GK) {
#pragma unroll
        for (int u = 0; u < 4; u++) fr[u] = F[(1 + u) * GK + j];
    }
    __syncthreads();

    for (int t = 1; t < GT; t += 4) {
#pragma unroll
        for (int u = 0; u < 4; u++) {
            const int tt = t + u;
            if (tt < GT) {  // uniform across block
                const float* vr = vbuf + (((tt - 1) & 1) << 6) + i0;
                float cand[28];
#pragma unroll
                for (int q = 0; q < 7; q++) {
                    float4 x = reinterpret_cast<const float4*>(vr)[q];
                    cand[4 * q]     = x.x + tr[4 * q];
                    cand[4 * q + 1] = x.y + tr[4 * q + 1];
                    cand[4 * q + 2] = x.z + tr[4 * q + 2];
                    cand[4 * q + 3] = x.w + tr[4 * q + 3];
                }
                int id[28];
#pragma unroll
                for (int ii = 0; ii < 28; ii++) id[ii] = i0 + ii;
                argmax_tree<28>(cand, id);
                float best = cand[0];
                int bi = id[0];

                // Single merge across r (lexicographic: lower idx wins ties)
                float ov = __shfl_xor_sync(0xffffffffu, best, 1);
                int   oi = __shfl_xor_sync(0xffffffffu, bi, 1);
                if (ov > best || (ov == best && oi < bi)) { best = ov; bi = oi; }

                if (r == 0 && j < GK) {
                    float* vw = vbuf + ((tt & 1) << 6);
                    vw[j] = fr[u] + best;
                    bp[(tt - 1) * BPP + j] = (unsigned char)bi;
                    int tn = tt + 4;
                    if (tn > GT - 1) tn = GT - 1;
                    fr[u] = F[tn * GK + j];
                }
                __syncthreads();
            }
        }
    }

    // Final: v at t=1023 lives in buffer half 1
    if (r == 0 && j < GK) red[j] = vbuf[64 + j] + stopt[j];
    __syncthreads();

    if (tid == 0) {
        float best = -INFINITY;
        int bj = 0;
        for (int k = 0; k < GK; k++) {
            float s = red[k];
            if (s > best) { best = s; bj = k; }
        }
        out[b] = best;
        int tag = bj;
        tags[GT - 1] = (unsigned char)tag;
        for (int k = GT - 2; k >= 0; k--) {
            tag = bp[k * BPP + tag];
            tags[k] = (unsigned char)tag;
        }
    }
    __syncthreads();

    // Parallel coalesced tag writeout
    float* tout = out + GB + (size_t)b * GT;
    for (int k = tid; k < GT; k += 128) tout[k] = (float)tags[k];
}

extern "C" void kernel_launch(void* const* d_in, const int* in_sizes, int n_in,
                              void* d_out, int out_size) {
    const float* hidden = (const float*)d_in[0];
    const float* W      = (const float*)d_in[1];
    const float* bias   = (const float*)d_in[2];
    const float* trans  = (const float*)d_in[3];
    const float* startt = (const float*)d_in[4];
    const float* stopt  = (const float*)d_in[5];
    float* out = (float*)d_out;

    const size_t gsm = (size_t)(WT_FLOATS + 2 * STG_FLOATS) * sizeof(float); // 188,416 B
    cudaFuncSetAttribute(gemm_kernel, cudaFuncAttributeMaxDynamicSharedMemorySize, (int)gsm);
    gemm_kernel<<<GM / RPC, 256, gsm>>>(hidden, W, bias);

    const size_t vsm = 53200 + (128 + 64) * sizeof(float) + 1024;            // 54,992 B
    cudaFuncSetAttribute(viterbi_kernel, cudaFuncAttributeMaxDynamicSharedMemorySize, (int)vsm);
    viterbi_kernel<<<GB, 128, vsm>>>(trans, startt, stopt, out);
}

// round 3
// speedup vs baseline: 1.4466x; 1.4466x over previous
#include <cuda_runtime.h>
#include <cstdint>
#include <cmath>

#define GH 512
#define GK 50
#define KPAD 52
#define GT 1024
#define GB 128
#define GM (GB * GT)
#define BPP 52

// Scratch for projected features [B*T, K]
__device__ float g_feats[(size_t)GM * GK];

// Packed fp32x2 FMA (sm_103a): acc = x * w + acc
#define FFMA2(acc, x, w) \
    asm("fma.rn.f32x2 %0, %1, %2, %0;" : "+l"(acc) : "l"(x), "l"(w))

// ---------------------------------------------------------------------------
// Kernel 1: feats[m][k] = sum_h hidden[m][h] * W[k][h] + b[k]
// 128 CTAs x 512 threads (SINGLE wave on 148 SMs), 2 rows/thread.
// Direct LDG of hidden (round-1 proven layout); W transposed in smem [h][52],
// broadcast LDS.128 conflict-free. All math in packed f32x2 FFMA.
// ---------------------------------------------------------------------------
__global__ __launch_bounds__(512, 1) void gemm_kernel(
    const float* __restrict__ hidden, const float* __restrict__ W,
    const float* __restrict__ bias) {
    extern __shared__ float Wt[];  // [GH][KPAD]
    const int tid = threadIdx.x;

    // Transpose W: W[k*512+h] -> Wt[h*52+k]  (coalesced gmem reads)
    for (int idx = tid; idx < GK * GH; idx += 512) {
        int k = idx >> 9;
        int h = idx & 511;
        Wt[h * KPAD + k] = W[idx];
    }
    __syncthreads();

    const size_t base = (size_t)blockIdx.x * 1024;
    const float4* r0 = reinterpret_cast<const float4*>(hidden + (base + tid) * GH);
    const float4* r1 = reinterpret_cast<const float4*>(hidden + (base + tid + 512) * GH);

    unsigned long long acc0[25], acc1[25];
#pragma unroll
    for (int q = 0; q < 25; q++) { acc0[q] = 0ull; acc1[q] = 0ull; }

    // Software-pipelined row loads: 8 h per chunk = 2 adjacent float4 per row
    float4 a0 = r0[0], a1 = r0[1];
    float4 b0 = r1[0], b1 = r1[1];

    for (int hc = 0; hc < 64; hc++) {
        float xs0[8] = {a0.x, a0.y, a0.z, a0.w, a1.x, a1.y, a1.z, a1.w};
        float xs1[8] = {b0.x, b0.y, b0.z, b0.w, b1.x, b1.y, b1.z, b1.w};
        if (hc < 63) {
            a0 = r0[2 * hc + 2]; a1 = r0[2 * hc + 3];
            b0 = r1[2 * hc + 2]; b1 = r1[2 * hc + 3];
        }
#pragma unroll
        for (int u = 0; u < 8; u++) {
            const int h = hc * 8 + u;
            unsigned long long X0, X1;
            asm("mov.b64 %0, {%1, %1};" : "=l"(X0) : "r"(__float_as_uint(xs0[u])));
            asm("mov.b64 %0, {%1, %1};" : "=l"(X1) : "r"(__float_as_uint(xs1[u])));
            const float* wr = Wt + h * KPAD;
#pragma unroll
            for (int q = 0; q < 12; q++) {
                ulonglong2 w = *reinterpret_cast<const ulonglong2*>(wr + q * 4);
                FFMA2(acc0[2 * q],     X0, w.x);
                FFMA2(acc0[2 * q + 1], X0, w.y);
                FFMA2(acc1[2 * q],     X1, w.x);
                FFMA2(acc1[2 * q + 1], X1, w.y);
            }
            unsigned long long wl = *reinterpret_cast<const unsigned long long*>(wr + 48);
            FFMA2(acc0[24], X0, wl);
            FFMA2(acc1[24], X1, wl);
        }
    }

    // Epilogue: add bias, write feats rows (float2 stores, 8B aligned: 50 even)
    float2* o0 = reinterpret_cast<float2*>(g_feats + (base + tid) * GK);
    float2* o1 = reinterpret_cast<float2*>(g_feats + (base + tid + 512) * GK);
    const float2* bb = reinterpret_cast<const float2*>(bias);
#pragma unroll
    for (int q = 0; q < 25; q++) {
        float2 bv = bb[q];
        float2 v0 = *reinterpret_cast<float2*>(&acc0[q]);
        float2 v1 = *reinterpret_cast<float2*>(&acc1[q]);
        v0.x += bv.x; v0.y += bv.y;
        v1.x += bv.x; v1.y += bv.y;
        o0[q] = v0;
        o1[q] = v1;
    }
}

// ---------------------------------------------------------------------------
// Pairwise argmax tree (select-form, 4-cyc pred-as-data links, NOT the
// 13-cyc pred-guard chain). Adjacent pairs keep index-ordered subranges, so
// strict '>' (right wins only if strictly greater) == jnp.argmax first-max.
// ---------------------------------------------------------------------------
template <int W>
__device__ __forceinline__ void argmax_tree(float* val, int* id) {
    if constexpr (W > 1) {
        constexpr int P = W >> 1;
#pragma unroll
        for (int m = 0; m < P; m++) {
            bool g = val[2 * m + 1] > val[2 * m];
            val[m] = g ? val[2 * m + 1] : val[2 * m];
            id[m]  = g ? id[2 * m + 1]  : id[2 * m];
        }
        if constexpr (W & 1) { val[P] = val[W - 1]; id[P] = id[W - 1]; }
        argmax_tree<((W + 1) >> 1)>(val, id);
    }
}

// ---------------------------------------------------------------------------
// Kernel 2: fused Viterbi forward + backtrace. One CTA (224 thr) per batch.
// Thread (j, r): j = tid>>2 (output state), r = tid&3 (13-wide i-slice).
// Tree argmax (depth 4) + two shfl merges. Backpointers entirely in smem so
// the backtrace is a 29-cycle LDS pointer chase.
// ---------------------------------------------------------------------------
__global__ __launch_bounds__(224, 1) void viterbi_kernel(
    const float* __restrict__ trans, const float* __restrict__ startt,
    const float* __restrict__ stopt, float* __restrict__ out) {
    extern __shared__ char smv[];
    unsigned char* bp = reinterpret_cast<unsigned char*>(smv);        // 1023*52
    float* vbuf = reinterpret_cast<float*>(smv + 53200);              // [2][64]
    float* red  = vbuf + 128;                                         // [64]
    unsigned char* tags = reinterpret_cast<unsigned char*>(red + 64); // [1024]

    const int b = blockIdx.x;
    const int tid = threadIdx.x;
    const int j = tid >> 2;
    const int r = tid & 3;
    const float* F = g_feats + (size_t)b * GT * GK;

    const int i0 = r * 13;

    // Per-thread transition slice trans[i][j] for i in [i0, i0+13), -inf pad
    float tr[13];
#pragma unroll
    for (int ii = 0; ii < 13; ii++) {
        int i = i0 + ii;
        tr[ii] = (j < GK && i < GK) ? trans[i * GK + j] : -INFINITY;
    }

    // Pad unused state slots with -inf in both v buffers
    if (tid >= GK && tid < 64) { vbuf[tid] = -INFINITY; vbuf[64 + tid] = -INFINITY; }
    // v at t=0
    if (r == 0 && j < GK) vbuf[j] = F[j] + startt[j];

    // Feats prefetch ring, depth 4 (~600 cycles ahead ~ DRAM latency)
    float fr[4];
    if (r == 0 && j < GK) {
#pragma unroll
        for (int u = 0; u < 4; u++) fr[u] = F[(1 + u) * GK + j];
    }
    __syncthreads();

    for (int t = 1; t < GT; t += 4) {
#pragma unroll
        for (int u = 0; u < 4; u++) {
            const int tt = t + u;
            if (tt < GT) {  // uniform across block: barrier inside is legal
                const float* vr = vbuf + (((tt - 1) & 1) << 6);
                float cand[13];
                int id[13];
#pragma unroll
                for (int ii = 0; ii < 13; ii++) {
                    cand[ii] = vr[i0 + ii] + tr[ii];
                    id[ii] = i0 + ii;
                }
                argmax_tree<13>(cand, id);
                float best = cand[0];
                int bi = id[0];

                // Combine 4 partial (val, idx) across r via butterfly shuffles
                float ov = __shfl_xor_sync(0xffffffffu, best, 1);
                int   oi = __shfl_xor_sync(0xffffffffu, bi, 1);
                bool g1 = (ov > best) || (ov == best && oi < bi);
                best = g1 ? ov : best;
                bi   = g1 ? oi : bi;
                ov = __shfl_xor_sync(0xffffffffu, best, 2);
                oi = __shfl_xor_sync(0xffffffffu, bi, 2);
                bool g2 = (ov > best) || (ov == best && oi < bi);
                best = g2 ? ov : best;
                bi   = g2 ? oi : bi;

                if (r == 0 && j < GK) {
                    float* vw = vbuf + ((tt & 1) << 6);
                    vw[j] = fr[u] + best;
                    bp[(tt - 1) * BPP + j] = (unsigned char)bi;
                    int tn = tt + 4;
                    if (tn > GT - 1) tn = GT - 1;
                    fr[u] = F[tn * GK + j];
                }
                __syncthreads();
            }
        }
    }

    // Final state: v at t=1023 lives in buffer half 1 (1023 & 1)
    if (r == 0 && j < GK) red[j] = vbuf[64 + j] + stopt[j];
    __syncthreads();

    if (tid == 0) {
        float best = -INFINITY;
        int bj = 0;
        for (int k = 0; k < GK; k++) {
            float s = red[k];
            if (s > best) { best = s; bj = k; }
        }
        out[b] = best;
        int tag = bj;
        tags[GT - 1] = (unsigned char)tag;
        for (int k = GT - 2; k >= 0; k--) {
            tag = bp[k * BPP + tag];
            tags[k] = (unsigned char)tag;
        }
    }
    __syncthreads();

    // Parallel coalesced tag writeout
    float* tout = out + GB + (size_t)b * GT;
    for (int k = tid; k < GT; k += 224) tout[k] = (float)tags[k];
}

extern "C" void kernel_launch(void* const* d_in, const int* in_sizes, int n_in,
                              void* d_out, int out_size) {
    const float* hidden = (const float*)d_in[0];
    const float* W      = (const float*)d_in[1];
    const float* bias   = (const float*)d_in[2];
    const float* trans  = (const float*)d_in[3];
    const float* startt = (const float*)d_in[4];
    const float* stopt  = (const float*)d_in[5];
    float* out = (float*)d_out;

    const size_t wsm = (size_t)GH * KPAD * sizeof(float);          // 106,496 B
    cudaFuncSetAttribute(gemm_kernel, cudaFuncAttributeMaxDynamicSharedMemorySize, (int)wsm);
    gemm_kernel<<<GM / 1024, 512, wsm>>>(hidden, W, bias);

    const size_t vsm = 53200 + (128 + 64) * sizeof(float) + 1024;  // 54,992 B
    cudaFuncSetAttribute(viterbi_kernel, cudaFuncAttributeMaxDynamicSharedMemorySize, (int)vsm);
    viterbi_kernel<<<GB, 224, vsm>>>(trans, startt, stopt, out);
}